// round 16
// baseline (speedup 1.0000x reference)
#include <cuda_runtime.h>

// GaussianPrimitives: Sigma = Q diag(exp(2*log_s)) Q^T,
// quaternion normalization folded into the rotmat (inv = 2/|q|^2).
//
// R4 structure (best measured: bench 42.1us, kernel 35.3us, DRAM 71.5%):
// warp-private shared-memory staging, all global accesses coalesced float4,
// conflict-free stride-3/stride-9 smem, __syncwarp-only.
// R16 single change: BLK 256 -> 128 (finer CTA allocation/drain granularity;
// warp-private structure makes block size otherwise semantically irrelevant).

#define BLK   128
#define WARPS (BLK / 32)

__device__ __forceinline__ void compute_sigma(float w, float x, float y, float z,
                                              float s0, float s1, float s2,
                                              float* r /*6 outs*/)
{
    float n2  = fmaf(w, w, fmaf(x, x, fmaf(y, y, z * z)));
    float inv = __fdividef(2.0f, n2);

    float xx = x * x, yy = y * y, zz = z * z;
    float xy = x * y, xz = x * z, yz = y * z;
    float wx = w * x, wy = w * y, wz = w * z;

    float r00 = 1.0f - inv * (yy + zz);
    float r01 = inv * (xy - wz);
    float r02 = inv * (xz + wy);
    float r10 = inv * (xy + wz);
    float r11 = 1.0f - inv * (xx + zz);
    float r12 = inv * (yz - wx);
    float r20 = inv * (xz - wy);
    float r21 = inv * (yz + wx);
    float r22 = 1.0f - inv * (xx + yy);

    float a0 = s0 * r00, a1 = s1 * r01, a2 = s2 * r02;
    float b0 = s0 * r10, b1 = s1 * r11, b2 = s2 * r12;
    float c0 = s0 * r20, c1 = s1 * r21, c2 = s2 * r22;

    r[0] = fmaf(a0, r00, fmaf(a1, r01, a2 * r02)); // s00
    r[1] = fmaf(a0, r10, fmaf(a1, r11, a2 * r12)); // s01
    r[2] = fmaf(a0, r20, fmaf(a1, r21, a2 * r22)); // s02
    r[3] = fmaf(b0, r10, fmaf(b1, r11, b2 * r12)); // s11
    r[4] = fmaf(b0, r20, fmaf(b1, r21, b2 * r22)); // s12
    r[5] = fmaf(c0, r20, fmaf(c1, r21, c2 * r22)); // s22
}

__global__ __launch_bounds__(BLK)
void gaussian_cov_kernel(const float4* __restrict__ q,
                         const float*  __restrict__ ls,
                         float* __restrict__ out,
                         int n)
{
    __shared__ float s_ls[WARPS][32 * 3];    //  1536 B total
    __shared__ float s_out[WARPS][32 * 9];   //  4608 B total

    int lane = threadIdx.x & 31;
    int w    = threadIdx.x >> 5;
    long long wbase = (long long)blockIdx.x * BLK + w * 32;   // first item of this warp

    if (wbase + 32 <= (long long)n) {
        // ---- fast path: full warp tile, warp-synchronous ----
        // stage log_s: 32*3 floats = 24 float4, coalesced
        const float4* lsv = (const float4*)(ls + wbase * 3);
        if (lane < 24) ((float4*)s_ls[w])[lane] = lsv[lane];

        float4 qv = q[wbase + lane];
        __syncwarp();

        float s0 = __expf(2.0f * s_ls[w][lane * 3 + 0]);
        float s1 = __expf(2.0f * s_ls[w][lane * 3 + 1]);
        float s2 = __expf(2.0f * s_ls[w][lane * 3 + 2]);

        float r[6];
        compute_sigma(qv.x, qv.y, qv.z, qv.w, s0, s1, s2, r);

        // stride-9 STS: gcd(9,32)=1 -> conflict-free
        float* so = s_out[w] + lane * 9;
        so[0] = r[0]; so[1] = r[1]; so[2] = r[2];
        so[3] = r[1]; so[4] = r[3]; so[5] = r[4];
        so[6] = r[2]; so[7] = r[4]; so[8] = r[5];
        __syncwarp();

        // stream out: 32*9 floats = 72 float4, coalesced
        float4* ov = (float4*)(out + wbase * 9);
        const float4* sv = (const float4*)s_out[w];
        ov[lane]      = sv[lane];
        ov[32 + lane] = sv[32 + lane];
        if (lane < 8) ov[64 + lane] = sv[64 + lane];
    } else {
        // ---- tail path: scalar (unused when N % 128 == 0) ----
        long long i = wbase + lane;
        if (i >= n) return;
        float4 qv = q[i];
        float s0 = __expf(2.0f * ls[3 * i + 0]);
        float s1 = __expf(2.0f * ls[3 * i + 1]);
        float s2 = __expf(2.0f * ls[3 * i + 2]);
        float r[6];
        compute_sigma(qv.x, qv.y, qv.z, qv.w, s0, s1, s2, r);
        float* o = out + 9 * i;
        o[0] = r[0]; o[1] = r[1]; o[2] = r[2];
        o[3] = r[1]; o[4] = r[3]; o[5] = r[4];
        o[6] = r[2]; o[7] = r[4]; o[8] = r[5];
    }
}

extern "C" void kernel_launch(void* const* d_in, const int* in_sizes, int n_in,
                              void* d_out, int out_size)
{
    const float4* q  = (const float4*)d_in[0];   // (N,4) float32
    const float*  ls = (const float*)d_in[1];    // (N,3) float32
    float* out = (float*)d_out;                  // (N,3,3) float32
    int n = in_sizes[0] / 4;

    int grid = (n + BLK - 1) / BLK;
    gaussian_cov_kernel<<<grid, BLK>>>(q, ls, out, n);
}

// round 17
// speedup vs baseline: 1.0236x; 1.0236x over previous
#include <cuda_runtime.h>

// FINAL — GaussianPrimitives: Sigma = Q diag(exp(2*log_s)) Q^T,
// quaternion normalization folded into the rotmat (inv = 2/|q|^2).
//
// Structure (R4, best measured across 16 rounds; 4 replications at
// 42.08-43.07us bench, kernel 35.3-36.5us, DRAM ~70-71.5%):
//  - one item per thread; warp-private shared-memory staging so every global
//    access is a coalesced float4 (LDG.128 / STG.128)
//  - stride-3 / stride-9 smem patterns are bank-conflict free (gcd with 32 = 1)
//  - __syncwarp-only synchronization; warps fully independent
//
// Effective throughput ~7.2 TB/s (~90% of HBM spec) counting L2 absorption —
// the practical roofline for this single-use mixed read/write stream.
// Measured-and-rejected levers: block tiles (R3), persistent grids (R5,R9),
// .cs load/store policies (R6,R11), TMA bulk store (R8), 256-bit I/O + evict
// hints (R13), createpolicy L2 pinning (R14), BLK=128 (R16).

#define BLK   256
#define WARPS (BLK / 32)

__device__ __forceinline__ void compute_sigma(float w, float x, float y, float z,
                                              float s0, float s1, float s2,
                                              float* r /*6 outs*/)
{
    float n2  = fmaf(w, w, fmaf(x, x, fmaf(y, y, z * z)));
    float inv = __fdividef(2.0f, n2);

    float xx = x * x, yy = y * y, zz = z * z;
    float xy = x * y, xz = x * z, yz = y * z;
    float wx = w * x, wy = w * y, wz = w * z;

    float r00 = 1.0f - inv * (yy + zz);
    float r01 = inv * (xy - wz);
    float r02 = inv * (xz + wy);
    float r10 = inv * (xy + wz);
    float r11 = 1.0f - inv * (xx + zz);
    float r12 = inv * (yz - wx);
    float r20 = inv * (xz - wy);
    float r21 = inv * (yz + wx);
    float r22 = 1.0f - inv * (xx + yy);

    float a0 = s0 * r00, a1 = s1 * r01, a2 = s2 * r02;
    float b0 = s0 * r10, b1 = s1 * r11, b2 = s2 * r12;
    float c0 = s0 * r20, c1 = s1 * r21, c2 = s2 * r22;

    r[0] = fmaf(a0, r00, fmaf(a1, r01, a2 * r02)); // s00
    r[1] = fmaf(a0, r10, fmaf(a1, r11, a2 * r12)); // s01
    r[2] = fmaf(a0, r20, fmaf(a1, r21, a2 * r22)); // s02
    r[3] = fmaf(b0, r10, fmaf(b1, r11, b2 * r12)); // s11
    r[4] = fmaf(b0, r20, fmaf(b1, r21, b2 * r22)); // s12
    r[5] = fmaf(c0, r20, fmaf(c1, r21, c2 * r22)); // s22
}

__global__ __launch_bounds__(BLK)
void gaussian_cov_kernel(const float4* __restrict__ q,
                         const float*  __restrict__ ls,
                         float* __restrict__ out,
                         int n)
{
    __shared__ float s_ls[WARPS][32 * 3];    //  3072 B total
    __shared__ float s_out[WARPS][32 * 9];   //  9216 B total

    int lane = threadIdx.x & 31;
    int w    = threadIdx.x >> 5;
    long long wbase = (long long)blockIdx.x * BLK + w * 32;   // first item of this warp

    if (wbase + 32 <= (long long)n) {
        // ---- fast path: full warp tile, warp-synchronous ----
        // stage log_s: 32*3 floats = 24 float4, coalesced
        const float4* lsv = (const float4*)(ls + wbase * 3);
        if (lane < 24) ((float4*)s_ls[w])[lane] = lsv[lane];

        float4 qv = q[wbase + lane];
        __syncwarp();

        float s0 = __expf(2.0f * s_ls[w][lane * 3 + 0]);
        float s1 = __expf(2.0f * s_ls[w][lane * 3 + 1]);
        float s2 = __expf(2.0f * s_ls[w][lane * 3 + 2]);

        float r[6];
        compute_sigma(qv.x, qv.y, qv.z, qv.w, s0, s1, s2, r);

        // stride-9 STS: gcd(9,32)=1 -> conflict-free
        float* so = s_out[w] + lane * 9;
        so[0] = r[0]; so[1] = r[1]; so[2] = r[2];
        so[3] = r[1]; so[4] = r[3]; so[5] = r[4];
        so[6] = r[2]; so[7] = r[4]; so[8] = r[5];
        __syncwarp();

        // stream out: 32*9 floats = 72 float4, coalesced
        float4* ov = (float4*)(out + wbase * 9);
        const float4* sv = (const float4*)s_out[w];
        ov[lane]      = sv[lane];
        ov[32 + lane] = sv[32 + lane];
        if (lane < 8) ov[64 + lane] = sv[64 + lane];
    } else {
        // ---- tail path: scalar (unused when N % 256 == 0) ----
        long long i = wbase + lane;
        if (i >= n) return;
        float4 qv = q[i];
        float s0 = __expf(2.0f * ls[3 * i + 0]);
        float s1 = __expf(2.0f * ls[3 * i + 1]);
        float s2 = __expf(2.0f * ls[3 * i + 2]);
        float r[6];
        compute_sigma(qv.x, qv.y, qv.z, qv.w, s0, s1, s2, r);
        float* o = out + 9 * i;
        o[0] = r[0]; o[1] = r[1]; o[2] = r[2];
        o[3] = r[1]; o[4] = r[3]; o[5] = r[4];
        o[6] = r[2]; o[7] = r[4]; o[8] = r[5];
    }
}

extern "C" void kernel_launch(void* const* d_in, const int* in_sizes, int n_in,
                              void* d_out, int out_size)
{
    const float4* q  = (const float4*)d_in[0];   // (N,4) float32
    const float*  ls = (const float*)d_in[1];    // (N,3) float32
    float* out = (float*)d_out;                  // (N,3,3) float32
    int n = in_sizes[0] / 4;

    int grid = (n + BLK - 1) / BLK;
    gaussian_cov_kernel<<<grid, BLK>>>(q, ls, out, n);
}